// round 4
// baseline (speedup 1.0000x reference)
#include <cuda_runtime.h>
#include <cuda_bf16.h>
#include <cstdint>

#define NN 50000
#define NE 600000
#define DD 128
#define NG 64

// ---------------- scratch (device globals; no allocation allowed) ----------------
__device__ float    g_dis[5 * NN];          // plane 0: unweighted, 1..4: per-head (deg -> rsqrt)
__device__ int      g_cnt[NN];
__device__ int      g_fill[NN];
__device__ int      g_rowptr[NN + 1];
__device__ int      g_bsum[64];
__device__ int      g_srcs[NE];
__device__ float    g_norm0[NE];
__device__ float    g_norm4[4 * NE];
__device__ float    g_Wt1[512 * 128];       // Wcat^T  [N=512][K=128]
__device__ float    g_Wt2[256 * 512];       // W2^T    [N=256][K=512]
__device__ float    g_Wt3[128 * 256];       // W3^T    [N=128][K=256]
__device__ float    g_bcat[512];
__device__ float    g_bufA[(size_t)NN * 512];
__device__ float    g_bufB[(size_t)NN * 512];
__device__ float    g_psum[NG * DD];
__device__ unsigned g_pmax[NG * DD];
__device__ int      g_pcnt[NG];

// ---------------- helpers ----------------
__device__ __forceinline__ unsigned encf(float f) {
    unsigned b = __float_as_uint(f);
    return (b & 0x80000000u) ? ~b : (b | 0x80000000u);
}
__device__ __forceinline__ float decf(unsigned u) {
    unsigned b = (u & 0x80000000u) ? (u & 0x7FFFFFFFu) : ~u;
    return __uint_as_float(b);
}
__device__ __forceinline__ uint32_t tf32r(float f) {
    uint32_t u;
    asm("cvt.rna.tf32.f32 %0, %1;" : "=r"(u) : "f"(f));
    return u;
}

// ---------------- zero scratch ----------------
__global__ void zero_all_k() {
    int i = blockIdx.x * blockDim.x + threadIdx.x;
    if (i < 5 * NN) g_dis[i] = 0.0f;
    if (i < NN) { g_cnt[i] = 0; g_fill[i] = 0; }
    if (i < NG * DD) { g_psum[i] = 0.0f; g_pmax[i] = 0u; }
    if (i < NG) g_pcnt[i] = 0;
}

// ---------------- degree + count ----------------
__global__ void degree_k(const int* __restrict__ ei, const float* __restrict__ attr) {
    int e = blockIdx.x * blockDim.x + threadIdx.x;
    if (e >= NE) return;
    int dst = ei[NE + e];
    atomicAdd(&g_dis[dst], 1.0f);
    atomicAdd(&g_cnt[dst], 1);
#pragma unroll
    for (int h = 0; h < 4; h++)
        atomicAdd(&g_dis[(h + 1) * NN + dst], attr[e * 4 + h]);
}

__global__ void finalize_dis_k() {
    int i = blockIdx.x * blockDim.x + threadIdx.x;
    if (i < 5 * NN) g_dis[i] = rsqrtf(g_dis[i] + 1.0f);   // +1 self loop; deg>=1 always
}

// ---------------- 3-phase multi-block scan over 50000 counts ----------------
__global__ void scan1_k() {
    __shared__ int ws[32];
    int b = blockIdx.x, t = threadIdx.x, lane = t & 31, w = t >> 5;
    int i = b * 1024 + t;
    int v = (i < NN) ? g_cnt[i] : 0;
    int inc = v;
#pragma unroll
    for (int off = 1; off < 32; off <<= 1) {
        int x = __shfl_up_sync(0xFFFFFFFFu, inc, off);
        if (lane >= off) inc += x;
    }
    if (lane == 31) ws[w] = inc;
    __syncthreads();
    if (w == 0) {
        int s = ws[lane];
#pragma unroll
        for (int off = 1; off < 32; off <<= 1) {
            int x = __shfl_up_sync(0xFFFFFFFFu, s, off);
            if (lane >= off) s += x;
        }
        ws[lane] = s;
    }
    __syncthreads();
    int pre = (w > 0) ? ws[w - 1] : 0;
    int incl = pre + inc;
    if (i < NN) g_rowptr[i + 1] = incl;
    if (t == 1023) g_bsum[b] = incl;
}
__global__ void scan2_k() {
    __shared__ int s[64];
    int t = threadIdx.x;
    int v = (t < 49) ? g_bsum[t] : 0;
    s[t] = v; __syncthreads();
    for (int off = 1; off < 64; off <<= 1) {
        int x = (t >= off) ? s[t - off] : 0;
        __syncthreads();
        s[t] += x;
        __syncthreads();
    }
    if (t < 49) g_bsum[t] = s[t] - v;   // exclusive
}
__global__ void scan3_k() {
    int b = blockIdx.x, t = threadIdx.x, i = b * 1024 + t;
    if (i < NN) g_rowptr[i + 1] += g_bsum[b];
    if (i == 0) g_rowptr[0] = 0;
}

// ---------------- scatter edges into CSR, precompute norms ----------------
__global__ void scatter_k(const int* __restrict__ ei, const float* __restrict__ attr) {
    int e = blockIdx.x * blockDim.x + threadIdx.x;
    if (e >= NE) return;
    int src = ei[e];
    int dst = ei[NE + e];
    int pos = g_rowptr[dst] + atomicAdd(&g_fill[dst], 1);
    g_srcs[pos] = src;
    g_norm0[pos] = g_dis[src] * g_dis[dst];
#pragma unroll
    for (int h = 0; h < 4; h++)
        g_norm4[pos * 4 + h] = g_dis[(h + 1) * NN + src] * attr[e * 4 + h] * g_dis[(h + 1) * NN + dst];
}

// ---------------- weight transposes ----------------
__global__ void pack1_k(const float* __restrict__ WA, const float* __restrict__ WB,
                        const float* __restrict__ WC, const float* __restrict__ WD,
                        const float* __restrict__ bA, const float* __restrict__ bB,
                        const float* __restrict__ bC, const float* __restrict__ bD) {
    int idx = blockIdx.x * blockDim.x + threadIdx.x;   // [0, 512*128)
    if (idx >= 512 * 128) return;
    int k = idx & 127, n = idx >> 7;
    int h = n >> 7, c = n & 127;
    const float* W = (h == 0) ? WA : (h == 1) ? WB : (h == 2) ? WC : WD;
    g_Wt1[idx] = W[k * 128 + c];
    if (k == 0) {
        const float* b = (h == 0) ? bA : (h == 1) ? bB : (h == 2) ? bC : bD;
        g_bcat[n] = b[c];
    }
}
__global__ void pack2_k(const float* __restrict__ W2) {
    int idx = blockIdx.x * blockDim.x + threadIdx.x;   // [0, 256*512)
    if (idx >= 256 * 512) return;
    int k = idx & 511, n = idx >> 9;
    g_Wt2[idx] = W2[k * 256 + n];
}
__global__ void pack3_k(const float* __restrict__ W3) {
    int idx = blockIdx.x * blockDim.x + threadIdx.x;   // [0, 128*256)
    if (idx >= 128 * 256) return;
    int k = idx & 255, n = idx >> 8;
    g_Wt3[idx] = W3[k * 128 + n];
}

// ---------------- tf32 mma.sync GEMM: C[M,N] = A[M,K] @ Bt[N,K]^T ----------------
// block tile 128x128, warp tile 64x32 (warp grid 2x4), K-tile 16, double-buffered.
// SMEM stride 20 words: bank sets {20n%32} = {0,20,8,28,16,4,24,12} -> frag LDS conflict-free.
#define SSTR 20

__device__ __forceinline__ void mma_tf32(float c[4], const uint32_t a[4], const uint32_t b[2]) {
    asm volatile(
        "mma.sync.aligned.m16n8k8.row.col.f32.tf32.tf32.f32 "
        "{%0,%1,%2,%3}, {%4,%5,%6,%7}, {%8,%9}, {%0,%1,%2,%3};\n"
        : "+f"(c[0]), "+f"(c[1]), "+f"(c[2]), "+f"(c[3])
        : "r"(a[0]), "r"(a[1]), "r"(a[2]), "r"(a[3]), "r"(b[0]), "r"(b[1]));
}

__global__ __launch_bounds__(256, 2) void mma_gemm_k(const float* __restrict__ A,
                                                     const float* __restrict__ Bt,
                                                     float* __restrict__ C,
                                                     int M, int N, int K) {
    __shared__ uint32_t As[2][128 * SSTR];
    __shared__ uint32_t Bs[2][128 * SSTR];
    int tid = threadIdx.x, wid = tid >> 5, lane = tid & 31;
    int row0 = blockIdx.y * 128, col0 = blockIdx.x * 128;
    int lr = tid >> 2, lc = (tid & 3) * 4;       // load map: row lr (+64), k-offset lc
    int wm = wid & 1, wn = wid >> 1;
    int grp = lane >> 2, qid = lane & 3;
    int mw = wm * 64, nw = wn * 32;

    float acc[4][4][4];
#pragma unroll
    for (int i = 0; i < 4; i++)
#pragma unroll
        for (int j = 0; j < 4; j++)
#pragma unroll
            for (int r = 0; r < 4; r++) acc[i][j][r] = 0.0f;

    float4 av0, av1, bv0, bv1;
    const float4 z4 = make_float4(0.f, 0.f, 0.f, 0.f);

    auto gload = [&](int t) {
        int k0 = t * 16;
        int gm0 = row0 + lr, gm1 = row0 + lr + 64;
        av0 = (gm0 < M) ? *reinterpret_cast<const float4*>(A + (size_t)gm0 * K + k0 + lc) : z4;
        av1 = (gm1 < M) ? *reinterpret_cast<const float4*>(A + (size_t)gm1 * K + k0 + lc) : z4;
        bv0 = *reinterpret_cast<const float4*>(Bt + (size_t)(col0 + lr) * K + k0 + lc);
        bv1 = *reinterpret_cast<const float4*>(Bt + (size_t)(col0 + lr + 64) * K + k0 + lc);
    };
    auto sstore = [&](int b) {
        uint4 u;
        u.x = tf32r(av0.x); u.y = tf32r(av0.y); u.z = tf32r(av0.z); u.w = tf32r(av0.w);
        *reinterpret_cast<uint4*>(&As[b][lr * SSTR + lc]) = u;
        u.x = tf32r(av1.x); u.y = tf32r(av1.y); u.z = tf32r(av1.z); u.w = tf32r(av1.w);
        *reinterpret_cast<uint4*>(&As[b][(lr + 64) * SSTR + lc]) = u;
        u.x = tf32r(bv0.x); u.y = tf32r(bv0.y); u.z = tf32r(bv0.z); u.w = tf32r(bv0.w);
        *reinterpret_cast<uint4*>(&Bs[b][lr * SSTR + lc]) = u;
        u.x = tf32r(bv1.x); u.y = tf32r(bv1.y); u.z = tf32r(bv1.z); u.w = tf32r(bv1.w);
        *reinterpret_cast<uint4*>(&Bs[b][(lr + 64) * SSTR + lc]) = u;
    };
    auto compute = [&](int b) {
        const uint32_t* as = As[b];
        const uint32_t* bs = Bs[b];
#pragma unroll
        for (int ks = 0; ks < 16; ks += 8) {
            uint32_t af[4][4], bf[4][2];
#pragma unroll
            for (int mf = 0; mf < 4; mf++) {
                int r = mw + mf * 16 + grp;
                af[mf][0] = as[r * SSTR + ks + qid];
                af[mf][1] = as[(r + 8) * SSTR + ks + qid];
                af[mf][2] = as[r * SSTR + ks + qid + 4];
                af[mf][3] = as[(r + 8) * SSTR + ks + qid + 4];
            }
#pragma unroll
            for (int nf = 0; nf < 4; nf++) {
                int cn = nw + nf * 8 + grp;
                bf[nf][0] = bs[cn * SSTR + ks + qid];
                bf[nf][1] = bs[cn * SSTR + ks + qid + 4];
            }
#pragma unroll
            for (int mf = 0; mf < 4; mf++)
#pragma unroll
                for (int nf = 0; nf < 4; nf++)
                    mma_tf32(acc[mf][nf], af[mf], bf[nf]);
        }
    };

    int ntiles = K >> 4;
    gload(0);
    sstore(0);
    __syncthreads();
    for (int t = 0; t < ntiles; t++) {
        if (t + 1 < ntiles) gload(t + 1);
        compute(t & 1);
        if (t + 1 < ntiles) {
            sstore((t + 1) & 1);
            __syncthreads();
        }
    }

    // epilogue
#pragma unroll
    for (int mf = 0; mf < 4; mf++) {
        int r0 = row0 + mw + mf * 16 + grp;
        int r1 = r0 + 8;
#pragma unroll
        for (int nf = 0; nf < 4; nf++) {
            int cc = col0 + nw + nf * 8 + 2 * qid;
            if (r0 < M)
                *reinterpret_cast<float2*>(C + (size_t)r0 * N + cc) =
                    make_float2(acc[mf][nf][0], acc[mf][nf][1]);
            if (r1 < M)
                *reinterpret_cast<float2*>(C + (size_t)r1 * N + cc) =
                    make_float2(acc[mf][nf][2], acc[mf][nf][3]);
        }
    }
}

// ---------------- stage-1 aggregation: 256-col panel, blocked lane map, vectorized ----------------
// lane owns columns [c0 + lane*8, c0 + lane*8 + 8); all 8 cols belong to ONE head:
// head = h0 + (lane >> 4).
__global__ __launch_bounds__(256) void agg1_k(const float* __restrict__ h,
                                              float* __restrict__ out, int c0) {
    int node = (blockIdx.x * blockDim.x + threadIdx.x) >> 5;
    if (node >= NN) return;
    int lane = threadIdx.x & 31;
    int h0 = c0 >> 7;
    int hd = h0 + (lane >> 4);                 // this lane's head (0..3)
    int coff = c0 + lane * 8;
    float d = g_dis[(hd + 1) * NN + node];
    float sn = d * d;                          // self-loop norm = 1/deg_w
    const float* hr = h + (size_t)node * 512 + coff;
    float4 s0 = *reinterpret_cast<const float4*>(hr);
    float4 s1 = *reinterpret_cast<const float4*>(hr + 4);
    float acc[8] = {sn * s0.x, sn * s0.y, sn * s0.z, sn * s0.w,
                    sn * s1.x, sn * s1.y, sn * s1.z, sn * s1.w};
    int beg = g_rowptr[node], end = g_rowptr[node + 1];
    for (int e = beg; e < end; e++) {
        int s = g_srcs[e];
        float nw = g_norm4[e * 4 + hd];
        const float* hs = h + (size_t)s * 512 + coff;
        float4 v0 = *reinterpret_cast<const float4*>(hs);
        float4 v1 = *reinterpret_cast<const float4*>(hs + 4);
        acc[0] = fmaf(nw, v0.x, acc[0]); acc[1] = fmaf(nw, v0.y, acc[1]);
        acc[2] = fmaf(nw, v0.z, acc[2]); acc[3] = fmaf(nw, v0.w, acc[3]);
        acc[4] = fmaf(nw, v1.x, acc[4]); acc[5] = fmaf(nw, v1.y, acc[5]);
        acc[6] = fmaf(nw, v1.z, acc[6]); acc[7] = fmaf(nw, v1.w, acc[7]);
    }
    const float4 bb0 = *reinterpret_cast<const float4*>(&g_bcat[coff]);
    const float4 bb1 = *reinterpret_cast<const float4*>(&g_bcat[coff + 4]);
    float4 o0 = make_float4(fmaxf(acc[0] + bb0.x, 0.f), fmaxf(acc[1] + bb0.y, 0.f),
                            fmaxf(acc[2] + bb0.z, 0.f), fmaxf(acc[3] + bb0.w, 0.f));
    float4 o1 = make_float4(fmaxf(acc[4] + bb1.x, 0.f), fmaxf(acc[5] + bb1.y, 0.f),
                            fmaxf(acc[6] + bb1.z, 0.f), fmaxf(acc[7] + bb1.w, 0.f));
    float* orow = out + (size_t)node * 512 + coff;
    *reinterpret_cast<float4*>(orow) = o0;
    *reinterpret_cast<float4*>(orow + 4) = o1;
}

// ---------------- uniform-norm aggregation, blocked lane map, vectorized ----------------
template <int DIM, bool RELU>
__global__ __launch_bounds__(256) void agg_uni_k(const float* __restrict__ h,
                                                 float* __restrict__ out,
                                                 const float* __restrict__ bias) {
    int node = (blockIdx.x * blockDim.x + threadIdx.x) >> 5;
    if (node >= NN) return;
    int lane = threadIdx.x & 31;
    constexpr int V = DIM / 32;                // 8 or 4 floats per lane, contiguous
    int coff = lane * V;
    float d0 = g_dis[node];
    float sn = d0 * d0;
    const float* hr = h + (size_t)node * DIM + coff;
    float acc[V];
#pragma unroll
    for (int q = 0; q < V; q += 4) {
        float4 v = *reinterpret_cast<const float4*>(hr + q);
        acc[q] = sn * v.x; acc[q + 1] = sn * v.y; acc[q + 2] = sn * v.z; acc[q + 3] = sn * v.w;
    }
    int beg = g_rowptr[node], end = g_rowptr[node + 1];
    for (int e = beg; e < end; e++) {
        int s = g_srcs[e];
        float nw = g_norm0[e];
        const float* hs = h + (size_t)s * DIM + coff;
#pragma unroll
        for (int q = 0; q < V; q += 4) {
            float4 v = *reinterpret_cast<const float4*>(hs + q);
            acc[q]     = fmaf(nw, v.x, acc[q]);
            acc[q + 1] = fmaf(nw, v.y, acc[q + 1]);
            acc[q + 2] = fmaf(nw, v.z, acc[q + 2]);
            acc[q + 3] = fmaf(nw, v.w, acc[q + 3]);
        }
    }
    float* orow = out + (size_t)node * DIM + coff;
#pragma unroll
    for (int q = 0; q < V; q += 4) {
        float4 bb = *reinterpret_cast<const float4*>(bias + coff + q);
        float4 o;
        o.x = acc[q] + bb.x; o.y = acc[q + 1] + bb.y;
        o.z = acc[q + 2] + bb.z; o.w = acc[q + 3] + bb.w;
        if (RELU) {
            o.x = fmaxf(o.x, 0.f); o.y = fmaxf(o.y, 0.f);
            o.z = fmaxf(o.z, 0.f); o.w = fmaxf(o.w, 0.f);
        }
        *reinterpret_cast<float4*>(orow + q) = o;
    }
}

// ---------------- pooling: batch sorted -> run-length accumulate + rare atomics ----------------
__global__ void pool_k(const float* __restrict__ h, const int* __restrict__ batch) {
    int d = threadIdx.x;
    int i0 = blockIdx.x * 128;
    if (i0 >= NN) return;
    int i1 = i0 + 128; if (i1 > NN) i1 = NN;
    int cur = batch[i0];
    float s = 0.0f, m = -3.4e38f;
    int c = 0;
    for (int i = i0; i < i1; i++) {
        int g = batch[i];
        if (g != cur) {
            atomicAdd(&g_psum[cur * DD + d], s);
            atomicMax(&g_pmax[cur * DD + d], encf(m));
            if (d == 0) atomicAdd(&g_pcnt[cur], c);
            cur = g; s = 0.0f; m = -3.4e38f; c = 0;
        }
        float v = h[(size_t)i * DD + d];
        s += v;
        m = fmaxf(m, v);
        c++;
    }
    atomicAdd(&g_psum[cur * DD + d], s);
    atomicMax(&g_pmax[cur * DD + d], encf(m));
    if (d == 0) atomicAdd(&g_pcnt[cur], c);
}

// ---------------- final MLP ----------------
__global__ void final_k(const float* __restrict__ Wm1, const float* __restrict__ bm1,
                        const float* __restrict__ Wm2, const float* __restrict__ bm2,
                        float* __restrict__ out) {
    __shared__ float feat[256];
    __shared__ float z[8];
    int g = blockIdx.x, t = threadIdx.x;
    int cnt = g_pcnt[g];
    if (t < 128) {
        feat[t] = g_psum[g * DD + t] / fmaxf((float)cnt, 1.0f);
    } else {
        float m = decf(g_pmax[g * DD + (t - 128)]);
        feat[t] = (cnt > 0) ? m : 0.0f;
    }
    __syncthreads();
    int w = t >> 5, lane = t & 31;
    float s = 0.0f;
#pragma unroll
    for (int u = 0; u < 8; u++) {
        int k = lane + 32 * u;
        s = fmaf(feat[k], Wm1[k * 8 + w], s);
    }
#pragma unroll
    for (int off = 16; off > 0; off >>= 1)
        s += __shfl_down_sync(0xFFFFFFFFu, s, off);
    if (lane == 0) {
        float v = s + bm1[w];
        z[w] = (v > 0.0f) ? v : 0.0f;
    }
    __syncthreads();
    if (t < 2) {
        float o = bm2[t];
#pragma unroll
        for (int j = 0; j < 8; j++) o = fmaf(z[j], Wm2[j * 2 + t], o);
        out[g * 2 + t] = o;
    }
}

// ---------------- host launch ----------------
extern "C" void kernel_launch(void* const* d_in, const int* in_sizes, int n_in,
                              void* d_out, int out_size) {
    const float* x    = (const float*)d_in[0];
    const int*   ei   = (const int*)d_in[1];
    const float* attr = (const float*)d_in[2];
    const int*   batch= (const int*)d_in[3];
    const float* W1A  = (const float*)d_in[4];
    const float* b1A  = (const float*)d_in[5];
    const float* W1B  = (const float*)d_in[6];
    const float* b1B  = (const float*)d_in[7];
    const float* W1C  = (const float*)d_in[8];
    const float* b1C  = (const float*)d_in[9];
    const float* W1D  = (const float*)d_in[10];
    const float* b1D  = (const float*)d_in[11];
    const float* W2   = (const float*)d_in[12];
    const float* b2   = (const float*)d_in[13];
    const float* W3   = (const float*)d_in[14];
    const float* b3   = (const float*)d_in[15];
    const float* Wm1  = (const float*)d_in[16];
    const float* bm1  = (const float*)d_in[17];
    const float* Wm2  = (const float*)d_in[18];
    const float* bm2  = (const float*)d_in[19];
    float* out = (float*)d_out;

    float *bufA, *bufB, *Wt1, *Wt2, *Wt3;
    cudaGetSymbolAddress((void**)&bufA, g_bufA);
    cudaGetSymbolAddress((void**)&bufB, g_bufB);
    cudaGetSymbolAddress((void**)&Wt1, g_Wt1);
    cudaGetSymbolAddress((void**)&Wt2, g_Wt2);
    cudaGetSymbolAddress((void**)&Wt3, g_Wt3);

    zero_all_k<<<(5 * NN + 255) / 256, 256>>>();
    degree_k<<<(NE + 255) / 256, 256>>>(ei, attr);
    finalize_dis_k<<<(5 * NN + 255) / 256, 256>>>();
    scan1_k<<<49, 1024>>>();
    scan2_k<<<1, 64>>>();
    scan3_k<<<49, 1024>>>();
    scatter_k<<<(NE + 255) / 256, 256>>>(ei, attr);
    pack1_k<<<(512 * 128 + 255) / 256, 256>>>(W1A, W1B, W1C, W1D, b1A, b1B, b1C, b1D);
    pack2_k<<<(256 * 512 + 255) / 256, 256>>>(W2);
    pack3_k<<<(128 * 256 + 255) / 256, 256>>>(W3);

    // GEMM1: bufA = x @ Wcat  [50000,512], K=128
    {
        dim3 grid(4, (NN + 127) / 128);
        mma_gemm_k<<<grid, 256>>>(x, Wt1, bufA, NN, 512, 128);
    }
    // AGG1 (2 column panels for L2 locality)
    agg1_k<<<(NN * 32 + 255) / 256, 256>>>(bufA, bufB, 0);
    agg1_k<<<(NN * 32 + 255) / 256, 256>>>(bufA, bufB, 256);
    // GEMM2: bufA = bufB @ W2  [50000,256], K=512
    {
        dim3 grid(2, (NN + 127) / 128);
        mma_gemm_k<<<grid, 256>>>(bufB, Wt2, bufA, NN, 256, 512);
    }
    agg_uni_k<256, true><<<(NN * 32 + 255) / 256, 256>>>(bufA, bufB, b2);
    // GEMM3: bufA = bufB @ W3  [50000,128], K=256
    {
        dim3 grid(1, (NN + 127) / 128);
        mma_gemm_k<<<grid, 256>>>(bufB, Wt3, bufA, NN, 128, 256);
    }
    agg_uni_k<128, false><<<(NN * 32 + 255) / 256, 256>>>(bufA, bufB, b3);
    pool_k<<<(NN + 127) / 128, 128>>>(bufB, batch);
    final_k<<<NG, 256>>>(Wm1, bm1, Wm2, bm2, out);
}

// round 5
// speedup vs baseline: 1.4904x; 1.4904x over previous
#include <cuda_runtime.h>
#include <cuda_bf16.h>
#include <cstdint>

#define NN 50000
#define NE 600000
#define DD 128
#define NG 64

// ---------------- scratch (device globals; no allocation allowed) ----------------
__device__ float    g_dis[5 * NN];          // plane 0: unweighted, 1..4: per-head (deg -> rsqrt)
__device__ int      g_cnt[NN];
__device__ int      g_fill[NN];
__device__ int      g_rowptr[NN + 1];
__device__ int      g_bsum[64];
__device__ int      g_srcs[NE];
__device__ float    g_norm0[NE];
__device__ float    g_norm4[4 * NE];
__device__ float    g_Wt1[512 * 128];       // Wcat^T  [N=512][K=128]
__device__ float    g_Wt2[256 * 512];       // W2^T    [N=256][K=512]
__device__ float    g_Wt3[128 * 256];       // W3^T    [N=128][K=256]
__device__ float    g_bcat[512];
__device__ float    g_bufA[(size_t)NN * 512];
__device__ float    g_bufB[(size_t)NN * 512];
__device__ float    g_psum[NG * DD];
__device__ unsigned g_pmax[NG * DD];
__device__ int      g_pcnt[NG];

// ---------------- helpers ----------------
__device__ __forceinline__ unsigned encf(float f) {
    unsigned b = __float_as_uint(f);
    return (b & 0x80000000u) ? ~b : (b | 0x80000000u);
}
__device__ __forceinline__ float decf(unsigned u) {
    unsigned b = (u & 0x80000000u) ? (u & 0x7FFFFFFFu) : ~u;
    return __uint_as_float(b);
}
__device__ __forceinline__ uint32_t tf32r(float f) {
    uint32_t u;
    asm("cvt.rna.tf32.f32 %0, %1;" : "=r"(u) : "f"(f));
    return u;
}

// ---------------- zero scratch ----------------
__global__ void zero_all_k() {
    int i = blockIdx.x * blockDim.x + threadIdx.x;
    if (i < 5 * NN) g_dis[i] = 0.0f;
    if (i < NN) { g_cnt[i] = 0; g_fill[i] = 0; }
    if (i < NG * DD) { g_psum[i] = 0.0f; g_pmax[i] = 0u; }
    if (i < NG) g_pcnt[i] = 0;
}

// ---------------- degree + count (attr as one float4) ----------------
__global__ void degree_k(const int* __restrict__ ei, const float* __restrict__ attr) {
    int e = blockIdx.x * blockDim.x + threadIdx.x;
    if (e >= NE) return;
    int dst = ei[NE + e];
    float4 a = *reinterpret_cast<const float4*>(attr + e * 4);
    atomicAdd(&g_dis[dst], 1.0f);
    atomicAdd(&g_cnt[dst], 1);
    atomicAdd(&g_dis[1 * NN + dst], a.x);
    atomicAdd(&g_dis[2 * NN + dst], a.y);
    atomicAdd(&g_dis[3 * NN + dst], a.z);
    atomicAdd(&g_dis[4 * NN + dst], a.w);
}

__global__ void finalize_dis_k() {
    int i = blockIdx.x * blockDim.x + threadIdx.x;
    if (i < 5 * NN) g_dis[i] = rsqrtf(g_dis[i] + 1.0f);   // +1 self loop; deg>=1 always
}

// ---------------- 3-phase multi-block scan over 50000 counts ----------------
__global__ void scan1_k() {
    __shared__ int ws[32];
    int b = blockIdx.x, t = threadIdx.x, lane = t & 31, w = t >> 5;
    int i = b * 1024 + t;
    int v = (i < NN) ? g_cnt[i] : 0;
    int inc = v;
#pragma unroll
    for (int off = 1; off < 32; off <<= 1) {
        int x = __shfl_up_sync(0xFFFFFFFFu, inc, off);
        if (lane >= off) inc += x;
    }
    if (lane == 31) ws[w] = inc;
    __syncthreads();
    if (w == 0) {
        int s = ws[lane];
#pragma unroll
        for (int off = 1; off < 32; off <<= 1) {
            int x = __shfl_up_sync(0xFFFFFFFFu, s, off);
            if (lane >= off) s += x;
        }
        ws[lane] = s;
    }
    __syncthreads();
    int pre = (w > 0) ? ws[w - 1] : 0;
    int incl = pre + inc;
    if (i < NN) g_rowptr[i + 1] = incl;
    if (t == 1023) g_bsum[b] = incl;
}
__global__ void scan2_k() {
    __shared__ int s[64];
    int t = threadIdx.x;
    int v = (t < 49) ? g_bsum[t] : 0;
    s[t] = v; __syncthreads();
    for (int off = 1; off < 64; off <<= 1) {
        int x = (t >= off) ? s[t - off] : 0;
        __syncthreads();
        s[t] += x;
        __syncthreads();
    }
    if (t < 49) g_bsum[t] = s[t] - v;   // exclusive
}
__global__ void scan3_k() {
    int b = blockIdx.x, t = threadIdx.x, i = b * 1024 + t;
    if (i < NN) g_rowptr[i + 1] += g_bsum[b];
    if (i == 0) g_rowptr[0] = 0;
}

// ---------------- scatter edges into CSR, precompute norms (attr float4) ----------------
__global__ void scatter_k(const int* __restrict__ ei, const float* __restrict__ attr) {
    int e = blockIdx.x * blockDim.x + threadIdx.x;
    if (e >= NE) return;
    int src = ei[e];
    int dst = ei[NE + e];
    float4 a = *reinterpret_cast<const float4*>(attr + e * 4);
    int pos = g_rowptr[dst] + atomicAdd(&g_fill[dst], 1);
    g_srcs[pos] = src;
    g_norm0[pos] = g_dis[src] * g_dis[dst];
    float4 nv;
    nv.x = g_dis[1 * NN + src] * a.x * g_dis[1 * NN + dst];
    nv.y = g_dis[2 * NN + src] * a.y * g_dis[2 * NN + dst];
    nv.z = g_dis[3 * NN + src] * a.z * g_dis[3 * NN + dst];
    nv.w = g_dis[4 * NN + src] * a.w * g_dis[4 * NN + dst];
    *reinterpret_cast<float4*>(g_norm4 + pos * 4) = nv;
}

// ---------------- weight transposes ----------------
__global__ void pack1_k(const float* __restrict__ WA, const float* __restrict__ WB,
                        const float* __restrict__ WC, const float* __restrict__ WD,
                        const float* __restrict__ bA, const float* __restrict__ bB,
                        const float* __restrict__ bC, const float* __restrict__ bD) {
    int idx = blockIdx.x * blockDim.x + threadIdx.x;   // [0, 512*128)
    if (idx >= 512 * 128) return;
    int k = idx & 127, n = idx >> 7;
    int h = n >> 7, c = n & 127;
    const float* W = (h == 0) ? WA : (h == 1) ? WB : (h == 2) ? WC : WD;
    g_Wt1[idx] = W[k * 128 + c];
    if (k == 0) {
        const float* b = (h == 0) ? bA : (h == 1) ? bB : (h == 2) ? bC : bD;
        g_bcat[n] = b[c];
    }
}
__global__ void pack2_k(const float* __restrict__ W2) {
    int idx = blockIdx.x * blockDim.x + threadIdx.x;   // [0, 256*512)
    if (idx >= 256 * 512) return;
    int k = idx & 511, n = idx >> 9;
    g_Wt2[idx] = W2[k * 256 + n];
}
__global__ void pack3_k(const float* __restrict__ W3) {
    int idx = blockIdx.x * blockDim.x + threadIdx.x;   // [0, 128*256)
    if (idx >= 128 * 256) return;
    int k = idx & 255, n = idx >> 8;
    g_Wt3[idx] = W3[k * 128 + n];
}

// ---------------- tf32 mma.sync GEMM: C[M,N] = A[M,K] @ Bt[N,K]^T ----------------
// block tile 128x128, warp tile 64x32 (warp grid 2x4), K-tile 16, double-buffered.
// SMEM stride 20 words: bank sets {20n%32} = {0,20,8,28,16,4,24,12} -> frag LDS conflict-free.
#define SSTR 20

__device__ __forceinline__ void mma_tf32(float c[4], const uint32_t a[4], const uint32_t b[2]) {
    asm volatile(
        "mma.sync.aligned.m16n8k8.row.col.f32.tf32.tf32.f32 "
        "{%0,%1,%2,%3}, {%4,%5,%6,%7}, {%8,%9}, {%0,%1,%2,%3};\n"
        : "+f"(c[0]), "+f"(c[1]), "+f"(c[2]), "+f"(c[3])
        : "r"(a[0]), "r"(a[1]), "r"(a[2]), "r"(a[3]), "r"(b[0]), "r"(b[1]));
}

__global__ __launch_bounds__(256, 2) void mma_gemm_k(const float* __restrict__ A,
                                                     const float* __restrict__ Bt,
                                                     float* __restrict__ C,
                                                     int M, int N, int K) {
    __shared__ uint32_t As[2][128 * SSTR];
    __shared__ uint32_t Bs[2][128 * SSTR];
    int tid = threadIdx.x, wid = tid >> 5, lane = tid & 31;
    int row0 = blockIdx.y * 128, col0 = blockIdx.x * 128;
    int lr = tid >> 2, lc = (tid & 3) * 4;       // load map: row lr (+64), k-offset lc
    int wm = wid & 1, wn = wid >> 1;
    int grp = lane >> 2, qid = lane & 3;
    int mw = wm * 64, nw = wn * 32;

    float acc[4][4][4];
#pragma unroll
    for (int i = 0; i < 4; i++)
#pragma unroll
        for (int j = 0; j < 4; j++)
#pragma unroll
            for (int r = 0; r < 4; r++) acc[i][j][r] = 0.0f;

    float4 av0, av1, bv0, bv1;
    const float4 z4 = make_float4(0.f, 0.f, 0.f, 0.f);

    auto gload = [&](int t) {
        int k0 = t * 16;
        int gm0 = row0 + lr, gm1 = row0 + lr + 64;
        av0 = (gm0 < M) ? *reinterpret_cast<const float4*>(A + (size_t)gm0 * K + k0 + lc) : z4;
        av1 = (gm1 < M) ? *reinterpret_cast<const float4*>(A + (size_t)gm1 * K + k0 + lc) : z4;
        bv0 = *reinterpret_cast<const float4*>(Bt + (size_t)(col0 + lr) * K + k0 + lc);
        bv1 = *reinterpret_cast<const float4*>(Bt + (size_t)(col0 + lr + 64) * K + k0 + lc);
    };
    auto sstore = [&](int b) {
        uint4 u;
        u.x = tf32r(av0.x); u.y = tf32r(av0.y); u.z = tf32r(av0.z); u.w = tf32r(av0.w);
        *reinterpret_cast<uint4*>(&As[b][lr * SSTR + lc]) = u;
        u.x = tf32r(av1.x); u.y = tf32r(av1.y); u.z = tf32r(av1.z); u.w = tf32r(av1.w);
        *reinterpret_cast<uint4*>(&As[b][(lr + 64) * SSTR + lc]) = u;
        u.x = tf32r(bv0.x); u.y = tf32r(bv0.y); u.z = tf32r(bv0.z); u.w = tf32r(bv0.w);
        *reinterpret_cast<uint4*>(&Bs[b][lr * SSTR + lc]) = u;
        u.x = tf32r(bv1.x); u.y = tf32r(bv1.y); u.z = tf32r(bv1.z); u.w = tf32r(bv1.w);
        *reinterpret_cast<uint4*>(&Bs[b][(lr + 64) * SSTR + lc]) = u;
    };
    auto compute = [&](int b) {
        const uint32_t* as = As[b];
        const uint32_t* bs = Bs[b];
#pragma unroll
        for (int ks = 0; ks < 16; ks += 8) {
            uint32_t af[4][4], bf[4][2];
#pragma unroll
            for (int mf = 0; mf < 4; mf++) {
                int r = mw + mf * 16 + grp;
                af[mf][0] = as[r * SSTR + ks + qid];
                af[mf][1] = as[(r + 8) * SSTR + ks + qid];
                af[mf][2] = as[r * SSTR + ks + qid + 4];
                af[mf][3] = as[(r + 8) * SSTR + ks + qid + 4];
            }
#pragma unroll
            for (int nf = 0; nf < 4; nf++) {
                int cn = nw + nf * 8 + grp;
                bf[nf][0] = bs[cn * SSTR + ks + qid];
                bf[nf][1] = bs[cn * SSTR + ks + qid + 4];
            }
#pragma unroll
            for (int mf = 0; mf < 4; mf++)
#pragma unroll
                for (int nf = 0; nf < 4; nf++)
                    mma_tf32(acc[mf][nf], af[mf], bf[nf]);
        }
    };

    int ntiles = K >> 4;
    gload(0);
    sstore(0);
    __syncthreads();
    for (int t = 0; t < ntiles; t++) {
        if (t + 1 < ntiles) gload(t + 1);
        compute(t & 1);
        if (t + 1 < ntiles) {
            sstore((t + 1) & 1);
            __syncthreads();
        }
    }

    // epilogue
#pragma unroll
    for (int mf = 0; mf < 4; mf++) {
        int r0 = row0 + mw + mf * 16 + grp;
        int r1 = r0 + 8;
#pragma unroll
        for (int nf = 0; nf < 4; nf++) {
            int cc = col0 + nw + nf * 8 + 2 * qid;
            if (r0 < M)
                *reinterpret_cast<float2*>(C + (size_t)r0 * N + cc) =
                    make_float2(acc[mf][nf][0], acc[mf][nf][1]);
            if (r1 < M)
                *reinterpret_cast<float2*>(C + (size_t)r1 * N + cc) =
                    make_float2(acc[mf][nf][2], acc[mf][nf][3]);
        }
    }
}

// ---------------- stage-1 aggregation: 2 heads per panel (256 cols), strided lanes ----------------
__global__ __launch_bounds__(256) void agg1_k(const float* __restrict__ h,
                                              float* __restrict__ out, int c0) {
    int node = (blockIdx.x * blockDim.x + threadIdx.x) >> 5;
    if (node >= NN) return;
    int lane = threadIdx.x & 31;
    int h0 = c0 >> 7;
    float acc[8];
    float sn[2];
#pragma unroll
    for (int jh = 0; jh < 2; jh++) {
        float d = g_dis[(h0 + jh + 1) * NN + node];
        sn[jh] = d * d;
    }
    const float* hr = h + (size_t)node * 512 + c0;
#pragma unroll
    for (int j = 0; j < 8; j++) acc[j] = sn[j >> 2] * hr[j * 32 + lane];
    int beg = g_rowptr[node], end = g_rowptr[node + 1];
    for (int e = beg; e < end; e++) {
        int s = g_srcs[e];
        const float* hs = h + (size_t)s * 512 + c0;
        float2 nr = *reinterpret_cast<const float2*>(g_norm4 + e * 4 + h0);
#pragma unroll
        for (int j = 0; j < 8; j++)
            acc[j] = fmaf((j < 4) ? nr.x : nr.y, hs[j * 32 + lane], acc[j]);
    }
    float* orow = out + (size_t)node * 512 + c0;
#pragma unroll
    for (int j = 0; j < 8; j++) {
        float v = acc[j] + g_bcat[c0 + j * 32 + lane];
        orow[j * 32 + lane] = (v > 0.0f) ? v : 0.0f;
    }
}

// ---------------- uniform-norm aggregation, strided lanes, templated dim ----------------
template <int DIM, bool RELU>
__global__ __launch_bounds__(256) void agg_uni_k(const float* __restrict__ h,
                                                 float* __restrict__ out,
                                                 const float* __restrict__ bias) {
    int node = (blockIdx.x * blockDim.x + threadIdx.x) >> 5;
    if (node >= NN) return;
    int lane = threadIdx.x & 31;
    constexpr int V = DIM / 32;
    float acc[V];
    float d0 = g_dis[node];
    float sn = d0 * d0;
    const float* hr = h + (size_t)node * DIM;
#pragma unroll
    for (int j = 0; j < V; j++) acc[j] = sn * hr[j * 32 + lane];
    int beg = g_rowptr[node], end = g_rowptr[node + 1];
    for (int e = beg; e < end; e++) {
        int s = g_srcs[e];
        float nw = g_norm0[e];
        const float* hs = h + (size_t)s * DIM;
#pragma unroll
        for (int j = 0; j < V; j++)
            acc[j] = fmaf(nw, hs[j * 32 + lane], acc[j]);
    }
    float* orow = out + (size_t)node * DIM;
#pragma unroll
    for (int j = 0; j < V; j++) {
        float v = acc[j] + bias[j * 32 + lane];
        if (RELU) v = (v > 0.0f) ? v : 0.0f;
        orow[j * 32 + lane] = v;
    }
}

// ---------------- pooling: batch sorted -> run-length accumulate + rare atomics ----------------
__global__ void pool_k(const float* __restrict__ h, const int* __restrict__ batch) {
    int d = threadIdx.x;
    int i0 = blockIdx.x * 128;
    if (i0 >= NN) return;
    int i1 = i0 + 128; if (i1 > NN) i1 = NN;
    int cur = batch[i0];
    float s = 0.0f, m = -3.4e38f;
    int c = 0;
    for (int i = i0; i < i1; i++) {
        int g = batch[i];
        if (g != cur) {
            atomicAdd(&g_psum[cur * DD + d], s);
            atomicMax(&g_pmax[cur * DD + d], encf(m));
            if (d == 0) atomicAdd(&g_pcnt[cur], c);
            cur = g; s = 0.0f; m = -3.4e38f; c = 0;
        }
        float v = h[(size_t)i * DD + d];
        s += v;
        m = fmaxf(m, v);
        c++;
    }
    atomicAdd(&g_psum[cur * DD + d], s);
    atomicMax(&g_pmax[cur * DD + d], encf(m));
    if (d == 0) atomicAdd(&g_pcnt[cur], c);
}

// ---------------- final MLP ----------------
__global__ void final_k(const float* __restrict__ Wm1, const float* __restrict__ bm1,
                        const float* __restrict__ Wm2, const float* __restrict__ bm2,
                        float* __restrict__ out) {
    __shared__ float feat[256];
    __shared__ float z[8];
    int g = blockIdx.x, t = threadIdx.x;
    int cnt = g_pcnt[g];
    if (t < 128) {
        feat[t] = g_psum[g * DD + t] / fmaxf((float)cnt, 1.0f);
    } else {
        float m = decf(g_pmax[g * DD + (t - 128)]);
        feat[t] = (cnt > 0) ? m : 0.0f;
    }
    __syncthreads();
    int w = t >> 5, lane = t & 31;
    float s = 0.0f;
#pragma unroll
    for (int u = 0; u < 8; u++) {
        int k = lane + 32 * u;
        s = fmaf(feat[k], Wm1[k * 8 + w], s);
    }
#pragma unroll
    for (int off = 16; off > 0; off >>= 1)
        s += __shfl_down_sync(0xFFFFFFFFu, s, off);
    if (lane == 0) {
        float v = s + bm1[w];
        z[w] = (v > 0.0f) ? v : 0.0f;
    }
    __syncthreads();
    if (t < 2) {
        float o = bm2[t];
#pragma unroll
        for (int j = 0; j < 8; j++) o = fmaf(z[j], Wm2[j * 2 + t], o);
        out[g * 2 + t] = o;
    }
}

// ---------------- host launch ----------------
extern "C" void kernel_launch(void* const* d_in, const int* in_sizes, int n_in,
                              void* d_out, int out_size) {
    const float* x    = (const float*)d_in[0];
    const int*   ei   = (const int*)d_in[1];
    const float* attr = (const float*)d_in[2];
    const int*   batch= (const int*)d_in[3];
    const float* W1A  = (const float*)d_in[4];
    const float* b1A  = (const float*)d_in[5];
    const float* W1B  = (const float*)d_in[6];
    const float* b1B  = (const float*)d_in[7];
    const float* W1C  = (const float*)d_in[8];
    const float* b1C  = (const float*)d_in[9];
    const float* W1D  = (const float*)d_in[10];
    const float* b1D  = (const float*)d_in[11];
    const float* W2   = (const float*)d_in[12];
    const float* b2   = (const float*)d_in[13];
    const float* W3   = (const float*)d_in[14];
    const float* b3   = (const float*)d_in[15];
    const float* Wm1  = (const float*)d_in[16];
    const float* bm1  = (const float*)d_in[17];
    const float* Wm2  = (const float*)d_in[18];
    const float* bm2  = (const float*)d_in[19];
    float* out = (float*)d_out;

    float *bufA, *bufB, *Wt1, *Wt2, *Wt3;
    cudaGetSymbolAddress((void**)&bufA, g_bufA);
    cudaGetSymbolAddress((void**)&bufB, g_bufB);
    cudaGetSymbolAddress((void**)&Wt1, g_Wt1);
    cudaGetSymbolAddress((void**)&Wt2, g_Wt2);
    cudaGetSymbolAddress((void**)&Wt3, g_Wt3);

    zero_all_k<<<(5 * NN + 255) / 256, 256>>>();
    degree_k<<<(NE + 255) / 256, 256>>>(ei, attr);
    finalize_dis_k<<<(5 * NN + 255) / 256, 256>>>();
    scan1_k<<<49, 1024>>>();
    scan2_k<<<1, 64>>>();
    scan3_k<<<49, 1024>>>();
    scatter_k<<<(NE + 255) / 256, 256>>>(ei, attr);
    pack1_k<<<(512 * 128 + 255) / 256, 256>>>(W1A, W1B, W1C, W1D, b1A, b1B, b1C, b1D);
    pack2_k<<<(256 * 512 + 255) / 256, 256>>>(W2);
    pack3_k<<<(128 * 256 + 255) / 256, 256>>>(W3);

    // GEMM1: bufA = x @ Wcat  [50000,512], K=128
    {
        dim3 grid(4, (NN + 127) / 128);
        mma_gemm_k<<<grid, 256>>>(x, Wt1, bufA, NN, 512, 128);
    }
    // AGG1 (2 column panels for L2 locality)
    agg1_k<<<(NN * 32 + 255) / 256, 256>>>(bufA, bufB, 0);
    agg1_k<<<(NN * 32 + 255) / 256, 256>>>(bufA, bufB, 256);
    // GEMM2: bufA = bufB @ W2  [50000,256], K=512
    {
        dim3 grid(2, (NN + 127) / 128);
        mma_gemm_k<<<grid, 256>>>(bufB, Wt2, bufA, NN, 256, 512);
    }
    agg_uni_k<256, true><<<(NN * 32 + 255) / 256, 256>>>(bufA, bufB, b2);
    // GEMM3: bufA = bufB @ W3  [50000,128], K=256
    {
        dim3 grid(1, (NN + 127) / 128);
        mma_gemm_k<<<grid, 256>>>(bufB, Wt3, bufA, NN, 128, 256);
    }
    agg_uni_k<128, false><<<(NN * 32 + 255) / 256, 256>>>(bufA, bufB, b3);
    pool_k<<<(NN + 127) / 128, 128>>>(bufB, batch);
    final_k<<<NG, 256>>>(Wm1, bm1, Wm2, bm2, out);
}

// round 6
// speedup vs baseline: 1.7258x; 1.1579x over previous
#include <cuda_runtime.h>
#include <cuda_bf16.h>
#include <cstdint>

#define NN 50000
#define NE 600000
#define DD 128
#define NG 64

// ---------------- scratch (device globals; no allocation allowed) ----------------
__device__ float    g_dis[5 * NN];          // plane 0: unweighted, 1..4: per-head (deg -> rsqrt)
__device__ int      g_cnt[NN];
__device__ int      g_fill[NN];
__device__ int      g_rowptr[NN + 1];
__device__ int      g_bsum[64];
__device__ int      g_srcs[NE];
__device__ float    g_norm0[NE];
__device__ float    g_norm4[4 * NE];
__device__ float    g_Wt1[512 * 128];       // Wcat^T  [N=512][K=128] (head h = rows h*128..)
__device__ float    g_Wt2[256 * 512];       // W2^T    [N=256][K=512]
__device__ float    g_Wt3[128 * 256];       // W3^T    [N=128][K=256]
__device__ float    g_bcat[512];
__device__ float    g_bufA[(size_t)NN * 512];
__device__ float    g_bufB[(size_t)NN * 512];
__device__ float    g_psum[NG * DD];
__device__ unsigned g_pmax[NG * DD];
__device__ int      g_pcnt[NG];

// ---------------- helpers ----------------
__device__ __forceinline__ unsigned encf(float f) {
    unsigned b = __float_as_uint(f);
    return (b & 0x80000000u) ? ~b : (b | 0x80000000u);
}
__device__ __forceinline__ float decf(unsigned u) {
    unsigned b = (u & 0x80000000u) ? (u & 0x7FFFFFFFu) : ~u;
    return __uint_as_float(b);
}
__device__ __forceinline__ uint32_t tf32r(float f) {
    uint32_t u;
    asm("cvt.rna.tf32.f32 %0, %1;" : "=r"(u) : "f"(f));
    return u;
}

// ---------------- zero scratch ----------------
__global__ void zero_all_k() {
    int i = blockIdx.x * blockDim.x + threadIdx.x;
    if (i < 5 * NN) g_dis[i] = 0.0f;
    if (i < NN) { g_cnt[i] = 0; g_fill[i] = 0; }
    if (i < NG * DD) { g_psum[i] = 0.0f; g_pmax[i] = 0u; }
    if (i < NG) g_pcnt[i] = 0;
}

// ---------------- degree + count ----------------
__global__ void degree_k(const int* __restrict__ ei, const float* __restrict__ attr) {
    int e = blockIdx.x * blockDim.x + threadIdx.x;
    if (e >= NE) return;
    int dst = ei[NE + e];
    float4 a = *reinterpret_cast<const float4*>(attr + e * 4);
    atomicAdd(&g_dis[dst], 1.0f);
    atomicAdd(&g_cnt[dst], 1);
    atomicAdd(&g_dis[1 * NN + dst], a.x);
    atomicAdd(&g_dis[2 * NN + dst], a.y);
    atomicAdd(&g_dis[3 * NN + dst], a.z);
    atomicAdd(&g_dis[4 * NN + dst], a.w);
}

__global__ void finalize_dis_k() {
    int i = blockIdx.x * blockDim.x + threadIdx.x;
    if (i < 5 * NN) g_dis[i] = rsqrtf(g_dis[i] + 1.0f);   // +1 self loop; deg>=1 always
}

// ---------------- 3-phase multi-block scan over 50000 counts ----------------
__global__ void scan1_k() {
    __shared__ int ws[32];
    int b = blockIdx.x, t = threadIdx.x, lane = t & 31, w = t >> 5;
    int i = b * 1024 + t;
    int v = (i < NN) ? g_cnt[i] : 0;
    int inc = v;
#pragma unroll
    for (int off = 1; off < 32; off <<= 1) {
        int x = __shfl_up_sync(0xFFFFFFFFu, inc, off);
        if (lane >= off) inc += x;
    }
    if (lane == 31) ws[w] = inc;
    __syncthreads();
    if (w == 0) {
        int s = ws[lane];
#pragma unroll
        for (int off = 1; off < 32; off <<= 1) {
            int x = __shfl_up_sync(0xFFFFFFFFu, s, off);
            if (lane >= off) s += x;
        }
        ws[lane] = s;
    }
    __syncthreads();
    int pre = (w > 0) ? ws[w - 1] : 0;
    int incl = pre + inc;
    if (i < NN) g_rowptr[i + 1] = incl;
    if (t == 1023) g_bsum[b] = incl;
}
__global__ void scan2_k() {
    __shared__ int s[64];
    int t = threadIdx.x;
    int v = (t < 49) ? g_bsum[t] : 0;
    s[t] = v; __syncthreads();
    for (int off = 1; off < 64; off <<= 1) {
        int x = (t >= off) ? s[t - off] : 0;
        __syncthreads();
        s[t] += x;
        __syncthreads();
    }
    if (t < 49) g_bsum[t] = s[t] - v;   // exclusive
}
__global__ void scan3_k() {
    int b = blockIdx.x, t = threadIdx.x, i = b * 1024 + t;
    if (i < NN) g_rowptr[i + 1] += g_bsum[b];
    if (i == 0) g_rowptr[0] = 0;
}

// ---------------- scatter edges into CSR, precompute norms ----------------
__global__ void scatter_k(const int* __restrict__ ei, const float* __restrict__ attr) {
    int e = blockIdx.x * blockDim.x + threadIdx.x;
    if (e >= NE) return;
    int src = ei[e];
    int dst = ei[NE + e];
    float4 a = *reinterpret_cast<const float4*>(attr + e * 4);
    int pos = g_rowptr[dst] + atomicAdd(&g_fill[dst], 1);
    g_srcs[pos] = src;
    g_norm0[pos] = g_dis[src] * g_dis[dst];
    float4 nv;
    nv.x = g_dis[1 * NN + src] * a.x * g_dis[1 * NN + dst];
    nv.y = g_dis[2 * NN + src] * a.y * g_dis[2 * NN + dst];
    nv.z = g_dis[3 * NN + src] * a.z * g_dis[3 * NN + dst];
    nv.w = g_dis[4 * NN + src] * a.w * g_dis[4 * NN + dst];
    *reinterpret_cast<float4*>(g_norm4 + pos * 4) = nv;
}

// ---------------- weight transposes ----------------
__global__ void pack1_k(const float* __restrict__ WA, const float* __restrict__ WB,
                        const float* __restrict__ WC, const float* __restrict__ WD,
                        const float* __restrict__ bA, const float* __restrict__ bB,
                        const float* __restrict__ bC, const float* __restrict__ bD) {
    int idx = blockIdx.x * blockDim.x + threadIdx.x;   // [0, 512*128)
    if (idx >= 512 * 128) return;
    int k = idx & 127, n = idx >> 7;
    int h = n >> 7, c = n & 127;
    const float* W = (h == 0) ? WA : (h == 1) ? WB : (h == 2) ? WC : WD;
    g_Wt1[idx] = W[k * 128 + c];
    if (k == 0) {
        const float* b = (h == 0) ? bA : (h == 1) ? bB : (h == 2) ? bC : bD;
        g_bcat[n] = b[c];
    }
}
__global__ void pack2_k(const float* __restrict__ W2) {
    int idx = blockIdx.x * blockDim.x + threadIdx.x;   // [0, 256*512)
    if (idx >= 256 * 512) return;
    int k = idx & 511, n = idx >> 9;
    g_Wt2[idx] = W2[k * 256 + n];
}
__global__ void pack3_k(const float* __restrict__ W3) {
    int idx = blockIdx.x * blockDim.x + threadIdx.x;   // [0, 128*256)
    if (idx >= 128 * 256) return;
    int k = idx & 255, n = idx >> 8;
    g_Wt3[idx] = W3[k * 128 + n];
}

// ---------------- fused 4-head aggregation of x (128 dims, one gather, 4 norms) ----------------
// out planes: out[h*NN*128 + node*128 + c]
__global__ __launch_bounds__(256) void aggx_k(const float* __restrict__ x,
                                              float* __restrict__ out) {
    int node = (blockIdx.x * blockDim.x + threadIdx.x) >> 5;
    if (node >= NN) return;
    int lane = threadIdx.x & 31;
    float sn[4];
#pragma unroll
    for (int h = 0; h < 4; h++) {
        float d = g_dis[(h + 1) * NN + node];
        sn[h] = d * d;                       // self-loop norm = 1/deg_w
    }
    const float* xr = x + (size_t)node * 128;
    float acc[4][4];
#pragma unroll
    for (int j = 0; j < 4; j++) {
        float v = xr[j * 32 + lane];
#pragma unroll
        for (int h = 0; h < 4; h++) acc[h][j] = sn[h] * v;
    }
    int beg = g_rowptr[node], end = g_rowptr[node + 1];
    for (int e = beg; e < end; e++) {
        int s = g_srcs[e];
        float4 nr = *reinterpret_cast<const float4*>(g_norm4 + (size_t)e * 4);
        const float* xs = x + (size_t)s * 128;
        float v0 = xs[lane], v1 = xs[32 + lane], v2 = xs[64 + lane], v3 = xs[96 + lane];
        acc[0][0] = fmaf(nr.x, v0, acc[0][0]); acc[0][1] = fmaf(nr.x, v1, acc[0][1]);
        acc[0][2] = fmaf(nr.x, v2, acc[0][2]); acc[0][3] = fmaf(nr.x, v3, acc[0][3]);
        acc[1][0] = fmaf(nr.y, v0, acc[1][0]); acc[1][1] = fmaf(nr.y, v1, acc[1][1]);
        acc[1][2] = fmaf(nr.y, v2, acc[1][2]); acc[1][3] = fmaf(nr.y, v3, acc[1][3]);
        acc[2][0] = fmaf(nr.z, v0, acc[2][0]); acc[2][1] = fmaf(nr.z, v1, acc[2][1]);
        acc[2][2] = fmaf(nr.z, v2, acc[2][2]); acc[2][3] = fmaf(nr.z, v3, acc[2][3]);
        acc[3][0] = fmaf(nr.w, v0, acc[3][0]); acc[3][1] = fmaf(nr.w, v1, acc[3][1]);
        acc[3][2] = fmaf(nr.w, v2, acc[3][2]); acc[3][3] = fmaf(nr.w, v3, acc[3][3]);
    }
#pragma unroll
    for (int h = 0; h < 4; h++) {
        float* orow = out + (size_t)h * NN * 128 + (size_t)node * 128;
#pragma unroll
        for (int j = 0; j < 4; j++) orow[j * 32 + lane] = acc[h][j];
    }
}

// ---------------- tf32 mma.sync GEMM: C[r*ldc + col0+c] = A_plane[M,K] @ Bt[*,K]^T ----------------
// block tile 128x128, warp tile 64x32 (warp grid 2x4), K-tile 16, double-buffered.
// A += blockIdx.x * aplane (per-head planes); optional bias+relu epilogue.
#define SSTR 20

__device__ __forceinline__ void mma_tf32(float c[4], const uint32_t a[4], const uint32_t b[2]) {
    asm volatile(
        "mma.sync.aligned.m16n8k8.row.col.f32.tf32.tf32.f32 "
        "{%0,%1,%2,%3}, {%4,%5,%6,%7}, {%8,%9}, {%0,%1,%2,%3};\n"
        : "+f"(c[0]), "+f"(c[1]), "+f"(c[2]), "+f"(c[3])
        : "r"(a[0]), "r"(a[1]), "r"(a[2]), "r"(a[3]), "r"(b[0]), "r"(b[1]));
}

__global__ __launch_bounds__(256, 2) void mma_gemm_k(const float* __restrict__ A,
                                                     const float* __restrict__ Bt,
                                                     float* __restrict__ C,
                                                     int M, int K, int ldc,
                                                     size_t aplane,
                                                     const float* __restrict__ bias,
                                                     int relu) {
    __shared__ uint32_t As[2][128 * SSTR];
    __shared__ uint32_t Bs[2][128 * SSTR];
    int tid = threadIdx.x, wid = tid >> 5, lane = tid & 31;
    int row0 = blockIdx.y * 128, col0 = blockIdx.x * 128;
    A += blockIdx.x * aplane;
    int lr = tid >> 2, lc = (tid & 3) * 4;
    int wm = wid & 1, wn = wid >> 1;
    int grp = lane >> 2, qid = lane & 3;
    int mw = wm * 64, nw = wn * 32;

    float acc[4][4][4];
#pragma unroll
    for (int i = 0; i < 4; i++)
#pragma unroll
        for (int j = 0; j < 4; j++)
#pragma unroll
            for (int r = 0; r < 4; r++) acc[i][j][r] = 0.0f;

    float4 av0, av1, bv0, bv1;
    const float4 z4 = make_float4(0.f, 0.f, 0.f, 0.f);

    auto gload = [&](int t) {
        int k0 = t * 16;
        int gm0 = row0 + lr, gm1 = row0 + lr + 64;
        av0 = (gm0 < M) ? *reinterpret_cast<const float4*>(A + (size_t)gm0 * K + k0 + lc) : z4;
        av1 = (gm1 < M) ? *reinterpret_cast<const float4*>(A + (size_t)gm1 * K + k0 + lc) : z4;
        bv0 = *reinterpret_cast<const float4*>(Bt + (size_t)(col0 + lr) * K + k0 + lc);
        bv1 = *reinterpret_cast<const float4*>(Bt + (size_t)(col0 + lr + 64) * K + k0 + lc);
    };
    auto sstore = [&](int b) {
        uint4 u;
        u.x = tf32r(av0.x); u.y = tf32r(av0.y); u.z = tf32r(av0.z); u.w = tf32r(av0.w);
        *reinterpret_cast<uint4*>(&As[b][lr * SSTR + lc]) = u;
        u.x = tf32r(av1.x); u.y = tf32r(av1.y); u.z = tf32r(av1.z); u.w = tf32r(av1.w);
        *reinterpret_cast<uint4*>(&As[b][(lr + 64) * SSTR + lc]) = u;
        u.x = tf32r(bv0.x); u.y = tf32r(bv0.y); u.z = tf32r(bv0.z); u.w = tf32r(bv0.w);
        *reinterpret_cast<uint4*>(&Bs[b][lr * SSTR + lc]) = u;
        u.x = tf32r(bv1.x); u.y = tf32r(bv1.y); u.z = tf32r(bv1.z); u.w = tf32r(bv1.w);
        *reinterpret_cast<uint4*>(&Bs[b][(lr + 64) * SSTR + lc]) = u;
    };
    auto compute = [&](int b) {
        const uint32_t* as = As[b];
        const uint32_t* bs = Bs[b];
#pragma unroll
        for (int ks = 0; ks < 16; ks += 8) {
            uint32_t af[4][4], bf[4][2];
#pragma unroll
            for (int mf = 0; mf < 4; mf++) {
                int r = mw + mf * 16 + grp;
                af[mf][0] = as[r * SSTR + ks + qid];
                af[mf][1] = as[(r + 8) * SSTR + ks + qid];
                af[mf][2] = as[r * SSTR + ks + qid + 4];
                af[mf][3] = as[(r + 8) * SSTR + ks + qid + 4];
            }
#pragma unroll
            for (int nf = 0; nf < 4; nf++) {
                int cn = nw + nf * 8 + grp;
                bf[nf][0] = bs[cn * SSTR + ks + qid];
                bf[nf][1] = bs[cn * SSTR + ks + qid + 4];
            }
#pragma unroll
            for (int mf = 0; mf < 4; mf++)
#pragma unroll
                for (int nf = 0; nf < 4; nf++)
                    mma_tf32(acc[mf][nf], af[mf], bf[nf]);
        }
    };

    int ntiles = K >> 4;
    gload(0);
    sstore(0);
    __syncthreads();
    for (int t = 0; t < ntiles; t++) {
        if (t + 1 < ntiles) gload(t + 1);
        compute(t & 1);
        if (t + 1 < ntiles) {
            sstore((t + 1) & 1);
            __syncthreads();
        }
    }

    // epilogue (optional bias + relu)
#pragma unroll
    for (int mf = 0; mf < 4; mf++) {
        int r0 = row0 + mw + mf * 16 + grp;
        int r1 = r0 + 8;
#pragma unroll
        for (int nf = 0; nf < 4; nf++) {
            int cc = col0 + nw + nf * 8 + 2 * qid;
            float2 v0 = make_float2(acc[mf][nf][0], acc[mf][nf][1]);
            float2 v1 = make_float2(acc[mf][nf][2], acc[mf][nf][3]);
            if (bias) {
                float2 bb = *reinterpret_cast<const float2*>(bias + cc);
                v0.x += bb.x; v0.y += bb.y;
                v1.x += bb.x; v1.y += bb.y;
            }
            if (relu) {
                v0.x = fmaxf(v0.x, 0.f); v0.y = fmaxf(v0.y, 0.f);
                v1.x = fmaxf(v1.x, 0.f); v1.y = fmaxf(v1.y, 0.f);
            }
            if (r0 < M) *reinterpret_cast<float2*>(C + (size_t)r0 * ldc + cc) = v0;
            if (r1 < M) *reinterpret_cast<float2*>(C + (size_t)r1 * ldc + cc) = v1;
        }
    }
}

// ---------------- uniform-norm aggregation, strided lanes, templated dim ----------------
template <int DIM, bool RELU>
__global__ __launch_bounds__(256) void agg_uni_k(const float* __restrict__ h,
                                                 float* __restrict__ out,
                                                 const float* __restrict__ bias) {
    int node = (blockIdx.x * blockDim.x + threadIdx.x) >> 5;
    if (node >= NN) return;
    int lane = threadIdx.x & 31;
    constexpr int V = DIM / 32;
    float acc[V];
    float d0 = g_dis[node];
    float sn = d0 * d0;
    const float* hr = h + (size_t)node * DIM;
#pragma unroll
    for (int j = 0; j < V; j++) acc[j] = sn * hr[j * 32 + lane];
    int beg = g_rowptr[node], end = g_rowptr[node + 1];
    for (int e = beg; e < end; e++) {
        int s = g_srcs[e];
        float nw = g_norm0[e];
        const float* hs = h + (size_t)s * DIM;
#pragma unroll
        for (int j = 0; j < V; j++)
            acc[j] = fmaf(nw, hs[j * 32 + lane], acc[j]);
    }
    float* orow = out + (size_t)node * DIM;
#pragma unroll
    for (int j = 0; j < V; j++) {
        float v = acc[j] + bias[j * 32 + lane];
        if (RELU) v = (v > 0.0f) ? v : 0.0f;
        orow[j * 32 + lane] = v;
    }
}

// ---------------- pooling: batch sorted -> run-length accumulate + rare atomics ----------------
__global__ void pool_k(const float* __restrict__ h, const int* __restrict__ batch) {
    int d = threadIdx.x;
    int i0 = blockIdx.x * 128;
    if (i0 >= NN) return;
    int i1 = i0 + 128; if (i1 > NN) i1 = NN;
    int cur = batch[i0];
    float s = 0.0f, m = -3.4e38f;
    int c = 0;
    for (int i = i0; i < i1; i++) {
        int g = batch[i];
        if (g != cur) {
            atomicAdd(&g_psum[cur * DD + d], s);
            atomicMax(&g_pmax[cur * DD + d], encf(m));
            if (d == 0) atomicAdd(&g_pcnt[cur], c);
            cur = g; s = 0.0f; m = -3.4e38f; c = 0;
        }
        float v = h[(size_t)i * DD + d];
        s += v;
        m = fmaxf(m, v);
        c++;
    }
    atomicAdd(&g_psum[cur * DD + d], s);
    atomicMax(&g_pmax[cur * DD + d], encf(m));
    if (d == 0) atomicAdd(&g_pcnt[cur], c);
}

// ---------------- final MLP ----------------
__global__ void final_k(const float* __restrict__ Wm1, const float* __restrict__ bm1,
                        const float* __restrict__ Wm2, const float* __restrict__ bm2,
                        float* __restrict__ out) {
    __shared__ float feat[256];
    __shared__ float z[8];
    int g = blockIdx.x, t = threadIdx.x;
    int cnt = g_pcnt[g];
    if (t < 128) {
        feat[t] = g_psum[g * DD + t] / fmaxf((float)cnt, 1.0f);
    } else {
        float m = decf(g_pmax[g * DD + (t - 128)]);
        feat[t] = (cnt > 0) ? m : 0.0f;
    }
    __syncthreads();
    int w = t >> 5, lane = t & 31;
    float s = 0.0f;
#pragma unroll
    for (int u = 0; u < 8; u++) {
        int k = lane + 32 * u;
        s = fmaf(feat[k], Wm1[k * 8 + w], s);
    }
#pragma unroll
    for (int off = 16; off > 0; off >>= 1)
        s += __shfl_down_sync(0xFFFFFFFFu, s, off);
    if (lane == 0) {
        float v = s + bm1[w];
        z[w] = (v > 0.0f) ? v : 0.0f;
    }
    __syncthreads();
    if (t < 2) {
        float o = bm2[t];
#pragma unroll
        for (int j = 0; j < 8; j++) o = fmaf(z[j], Wm2[j * 2 + t], o);
        out[g * 2 + t] = o;
    }
}

// ---------------- host launch ----------------
extern "C" void kernel_launch(void* const* d_in, const int* in_sizes, int n_in,
                              void* d_out, int out_size) {
    const float* x    = (const float*)d_in[0];
    const int*   ei   = (const int*)d_in[1];
    const float* attr = (const float*)d_in[2];
    const int*   batch= (const int*)d_in[3];
    const float* W1A  = (const float*)d_in[4];
    const float* b1A  = (const float*)d_in[5];
    const float* W1B  = (const float*)d_in[6];
    const float* b1B  = (const float*)d_in[7];
    const float* W1C  = (const float*)d_in[8];
    const float* b1C  = (const float*)d_in[9];
    const float* W1D  = (const float*)d_in[10];
    const float* b1D  = (const float*)d_in[11];
    const float* W2   = (const float*)d_in[12];
    const float* b2   = (const float*)d_in[13];
    const float* W3   = (const float*)d_in[14];
    const float* b3   = (const float*)d_in[15];
    const float* Wm1  = (const float*)d_in[16];
    const float* bm1  = (const float*)d_in[17];
    const float* Wm2  = (const float*)d_in[18];
    const float* bm2  = (const float*)d_in[19];
    float* out = (float*)d_out;

    float *bufA, *bufB, *Wt1, *Wt2, *Wt3, *bcat;
    cudaGetSymbolAddress((void**)&bufA, g_bufA);
    cudaGetSymbolAddress((void**)&bufB, g_bufB);
    cudaGetSymbolAddress((void**)&Wt1, g_Wt1);
    cudaGetSymbolAddress((void**)&Wt2, g_Wt2);
    cudaGetSymbolAddress((void**)&Wt3, g_Wt3);
    cudaGetSymbolAddress((void**)&bcat, g_bcat);

    zero_all_k<<<(5 * NN + 255) / 256, 256>>>();
    degree_k<<<(NE + 255) / 256, 256>>>(ei, attr);
    finalize_dis_k<<<(5 * NN + 255) / 256, 256>>>();
    scan1_k<<<49, 1024>>>();
    scan2_k<<<1, 64>>>();
    scan3_k<<<49, 1024>>>();
    scatter_k<<<(NE + 255) / 256, 256>>>(ei, attr);
    pack1_k<<<(512 * 128 + 255) / 256, 256>>>(W1A, W1B, W1C, W1D, b1A, b1B, b1C, b1D);
    pack2_k<<<(256 * 512 + 255) / 256, 256>>>(W2);
    pack3_k<<<(128 * 256 + 255) / 256, 256>>>(W3);

    // LAYER 1: aggregate x once (4 heads fused) -> bufA planes [4][NN,128]
    aggx_k<<<(NN * 32 + 255) / 256, 256>>>(x, bufA);
    // 4 per-head GEMMs [NN,128]@[128,128] + bias + relu -> bufB [NN,512] concat layout
    {
        dim3 grid(4, (NN + 127) / 128);
        mma_gemm_k<<<grid, 256>>>(bufA, Wt1, bufB, NN, 128, 512,
                                  (size_t)NN * 128, bcat, 1);
    }
    // LAYER 2: GEMM [NN,512]@[512,256] -> bufA, then agg+bias+relu -> bufB
    {
        dim3 grid(2, (NN + 127) / 128);
        mma_gemm_k<<<grid, 256>>>(bufB, Wt2, bufA, NN, 512, 256, 0, nullptr, 0);
    }
    agg_uni_k<256, true><<<(NN * 32 + 255) / 256, 256>>>(bufA, bufB, b2);
    // LAYER 3: GEMM [NN,256]@[256,128] -> bufA, then agg+bias -> bufB
    {
        dim3 grid(1, (NN + 127) / 128);
        mma_gemm_k<<<grid, 256>>>(bufB, Wt3, bufA, NN, 256, 128, 0, nullptr, 0);
    }
    agg_uni_k<128, false><<<(NN * 32 + 255) / 256, 256>>>(bufA, bufB, b3);
    pool_k<<<(NN + 127) / 128, 128>>>(bufB, batch);
    final_k<<<NG, 256>>>(Wm1, bm1, Wm2, bm2, out);
}